// round 10
// baseline (speedup 1.0000x reference)
#include <cuda_runtime.h>
#include <cuda_bf16.h>

// ODE-GRU: B=128, L=2048, I=D=64.
// Round 10: R5 skeleton (1 CTA/batch, 256 thr, 2 reg-resident packed rows/
// thread, 512 dots/step) + dependency-precise NAMED barriers:
//   serial chain t1 -> hode -> gh -> gates no longer waits on the wide gx
//   GEMV (overlaps P2/P3); gates preload gx/ho at bar2; prefetch commits
//   moved off the gates path. tanh.approx for t1 only (error damped ~1e-2).
// Barriers: bar1(128): t1 ready; bar2(256): hode+gx ready; bar3(192):
// gh ready; one full __syncthreads per step publishes h/x/dt.

#define NB 128
#define NL 2048
#define ND 64
#define NG 192

typedef unsigned long long u64;

#define BAR_SYNC(id, cnt)   asm volatile("bar.sync %0, %1;"   :: "r"(id), "r"(cnt) : "memory")
#define BAR_ARRIVE(id, cnt) asm volatile("bar.arrive %0, %1;" :: "r"(id), "r"(cnt) : "memory")

__device__ __forceinline__ u64 fma2(u64 a, u64 b, u64 c) {
    u64 d;
    asm("fma.rn.f32x2 %0, %1, %2, %3;" : "=l"(d) : "l"(a), "l"(b), "l"(c));
    return d;
}
__device__ __forceinline__ u64 add2(u64 a, u64 b) {
    u64 d;
    asm("add.rn.f32x2 %0, %1, %2;" : "=l"(d) : "l"(a), "l"(b));
    return d;
}
__device__ __forceinline__ u64 pk(float lo, float hi) {
    u64 r;
    asm("mov.b64 %0, {%1, %2};" : "=l"(r) : "f"(lo), "f"(hi));
    return r;
}

// dot(w_row[64], v[64]) + bias, w pre-packed f32x2 (bias seeded in acc).
__device__ __forceinline__ float dot64p(const u64* __restrict__ w,
                                        const float* __restrict__ v,
                                        float bias)
{
    const ulonglong2* __restrict__ v2 = (const ulonglong2*)v;
    u64 a0 = pk(bias, 0.f), a1 = 0ull, a2 = 0ull, a3 = 0ull;
#pragma unroll
    for (int q = 0; q < 8; q++) {
        ulonglong2 p = v2[2*q];
        ulonglong2 r = v2[2*q + 1];
        a0 = fma2(w[4*q+0], p.x, a0);
        a1 = fma2(w[4*q+1], p.y, a1);
        a2 = fma2(w[4*q+2], r.x, a2);
        a3 = fma2(w[4*q+3], r.y, a3);
    }
    u64 s = add2(add2(a0, a1), add2(a2, a3));
    return __uint_as_float((unsigned)s) + __uint_as_float((unsigned)(s >> 32));
}

__device__ __forceinline__ float sigmoidf_(float a) {      // precise (gates)
    return __fdividef(1.f, 1.f + __expf(-a));
}
__device__ __forceinline__ float tanhf_fast(float x) {     // precise (n-gate)
    float e = __expf(2.f * x);
    return 1.f - __fdividef(2.f, e + 1.f);
}
__device__ __forceinline__ float tanh_ap(float x) {        // approx (t1 only)
    float y;
    asm("tanh.approx.f32 %0, %1;" : "=f"(y) : "f"(x));
    return y;
}

__global__ __launch_bounds__(256, 1)
void odegru_kernel(const float* __restrict__ x,
                   const float* __restrict__ tdel,
                   const int*   __restrict__ seq,
                   const float* __restrict__ h0,
                   const float* __restrict__ w_ih,
                   const float* __restrict__ w_hh,
                   const float* __restrict__ b_ih,
                   const float* __restrict__ b_hh,
                   const float* __restrict__ dw1,
                   const float* __restrict__ db1,
                   const float* __restrict__ dw2,
                   const float* __restrict__ db2,
                   float* __restrict__ out)
{
    const int b   = blockIdx.x;
    const int tid = threadIdx.x;

    __shared__ __align__(16) float sh_h[ND];
    __shared__ __align__(16) float sh_t1[ND];
    __shared__ __align__(16) float sh_ho[ND];
    __shared__ __align__(16) float sh_gx[NG];
    __shared__ __align__(16) float sh_gh[128];   // rows 0..127 (128+j in reg)
    __shared__ __align__(16) float sh_x[2][ND];
    __shared__ float sh_dt[2];

    // ---- packed weight rows (2/thread), identical role split to R5 ----
    // t0-63  : wX = dw1 row j        (t1)    wY = w_hh row 128+j (gh hi)
    // t64-127: wX = dw2 row j        (hode)  wY = w_ih row j     (gx lo)
    // t128-255:wX = w_hh row tid-128 (gh lo) wY = w_ih row tid-64(gx hi)
    u64 wX[32], wY[32];
    float bX, bY;
    const float* pX;
    const float* pY;
    if (tid < 64) {
        pX = dw1 + tid * 64;          bX = db1[tid];
        pY = w_hh + (128 + tid) * 64; bY = b_hh[128 + tid];
    } else if (tid < 128) {
        int j = tid - 64;
        pX = dw2 + j * 64;            bX = db2[j];
        pY = w_ih + j * 64;           bY = b_ih[j];
    } else {
        pX = w_hh + (tid - 128) * 64; bX = b_hh[tid - 128];
        pY = w_ih + (tid - 64) * 64;  bY = b_ih[tid - 64];
    }
#pragma unroll
    for (int k = 0; k < 32; k++) {
        wX[k] = ((const u64*)pX)[k];
        wY[k] = ((const u64*)pY)[k];
    }

    const int sl = seq[b];
    const float* xb  = x + (size_t)b * NL * ND;
    const float* dtb = tdel + (size_t)b * NL;
    float* outb      = out + (size_t)b * NL * ND;

    if (tid < 64) sh_h[tid] = h0[tid];
    if (tid >= 64 && tid < 128) sh_x[0][tid - 64] = xb[tid - 64];  // t=0 live
    if (tid == 64) sh_dt[0] = dtb[0];

    float fin = 0.f;
    __syncthreads();

    for (int t = 0; t < NL; t++) {
        const int cur = t & 1, nxt = cur ^ 1;
        const int tn  = t + 1;

        if (tid < 64) {
            const int j = tid;
            // P1: t1 = tanh(h*dw1^T + db1)   (approx tanh: damped by dt*dw2)
            sh_t1[j] = tanh_ap(dot64p(wX, sh_h, bX));
            BAR_ARRIVE(1, 128);
            // wait hode (+ all gx rows, transitively visible at release)
            BAR_SYNC(2, 256);
            float gx0 = sh_gx[j];
            float gx1 = sh_gx[64 + j];
            float gx2 = sh_gx[128 + j];
            float ho  = sh_ho[j];
            // P3: gh[128+j], kept in register
            float gn = dot64p(wY, sh_ho, bY);
            BAR_SYNC(3, 192);
            // P4: gates
            float r  = sigmoidf_(gx0 + sh_gh[j]);
            float z  = sigmoidf_(gx1 + sh_gh[64 + j]);
            float n  = tanhf_fast(fmaf(r, gn, gx2));
            float hn = fmaf(z, ho - n, n);        // (1-z)*n + z*ho
            sh_h[j] = hn;
            outb[(size_t)t * ND + j] = hn;
            if (t == sl - 1) fin = hn;
        } else if (tid < 128) {
            const int j = tid - 64;
            // prefetch x/dt for t+1 (LDG latency covered by gx+hode dots)
            float xr = 0.f, dtr = 0.f;
            if (tn < NL) {
                xr = xb[(size_t)tn * ND + j];
                if (tid == 64) dtr = dtb[tn];
            }
            // P1: gx rows 0..63
            sh_gx[j] = dot64p(wY, sh_x[cur], bY);
            BAR_SYNC(1, 128);                     // wait t1
            // P2: h_ode = h + (t1*dw2^T + db2)*dt
            float d = dot64p(wX, sh_t1, bX);
            sh_ho[j] = fmaf(d, sh_dt[cur], sh_h[j]);
            BAR_ARRIVE(2, 256);
            // commit prefetch (PaddedBatch mask) off the gates path
            sh_x[nxt][j] = (tn < sl) ? xr : 0.f;
            if (tid == 64) sh_dt[nxt] = (tn < sl) ? dtr : 0.f;
        } else {
            const int r1 = tid - 64;              // gx row 64..191
            // P1: gx rows 64..191
            sh_gx[r1] = dot64p(wY, sh_x[cur], bY);
            BAR_SYNC(2, 256);                     // wait hode
            // P3: gh rows 0..127
            sh_gh[tid - 128] = dot64p(wX, sh_ho, bX);
            BAR_ARRIVE(3, 192);
        }
        __syncthreads();                          // publish h, x[nxt], dt[nxt]
    }

    // final hidden state -> second output tensor (1, B, D)
    if (tid < 64)
        out[(size_t)NB * NL * ND + (size_t)b * ND + tid] = fin;
}

extern "C" void kernel_launch(void* const* d_in, const int* in_sizes, int n_in,
                              void* d_out, int out_size)
{
    const float* x    = (const float*)d_in[0];
    const float* tdel = (const float*)d_in[1];
    const int*   seq  = (const int*)  d_in[2];
    const float* h0   = (const float*)d_in[3];
    const float* w_ih = (const float*)d_in[4];
    const float* w_hh = (const float*)d_in[5];
    const float* b_ih = (const float*)d_in[6];
    const float* b_hh = (const float*)d_in[7];
    const float* dw1  = (const float*)d_in[8];
    const float* db1  = (const float*)d_in[9];
    const float* dw2  = (const float*)d_in[10];
    const float* db2  = (const float*)d_in[11];

    odegru_kernel<<<NB, 256>>>(x, tdel, seq, h0, w_ih, w_hh, b_ih, b_hh,
                               dw1, db1, dw2, db2, (float*)d_out);
}

// round 11
// speedup vs baseline: 1.4529x; 1.4529x over previous
#include <cuda_runtime.h>
#include <cuda_bf16.h>

// ODE-GRU: B=128, L=2048, I=D=64.
// Round 11: R5 skeleton EXACTLY (1 CTA/batch, 256 thr, 4 full __syncthreads,
// 2 reg-resident packed rows/thread, 512 dots/step) with within-structure
// critical-path trims only:
//  - tanh.approx for t1 (validated R10: error damped by dt*dw2, rel_err 6e-7)
//  - threads 0-63 preload gx[j],gx[64+j],gx[128+j] in their P2 idle window
//  - x/dt prefetch owned by threads 64-127's idle windows (commit t+1 after
//    sync2, issue LDG for t+2 there; ~1365cyc cover) -> nothing extra on the
//    thread-0-63 path
//  - ho picked up at P3 entry (overlaps gh dot)
// Gates remain __expf-precise (approx there risks 1e-3 over 2048 steps).

#define NB 128
#define NL 2048
#define ND 64
#define NG 192

typedef unsigned long long u64;

__device__ __forceinline__ u64 fma2(u64 a, u64 b, u64 c) {
    u64 d;
    asm("fma.rn.f32x2 %0, %1, %2, %3;" : "=l"(d) : "l"(a), "l"(b), "l"(c));
    return d;
}
__device__ __forceinline__ u64 add2(u64 a, u64 b) {
    u64 d;
    asm("add.rn.f32x2 %0, %1, %2;" : "=l"(d) : "l"(a), "l"(b));
    return d;
}
__device__ __forceinline__ u64 pk(float lo, float hi) {
    u64 r;
    asm("mov.b64 %0, {%1, %2};" : "=l"(r) : "f"(lo), "f"(hi));
    return r;
}

// dot(w_row[64], v[64]) + bias, w pre-packed f32x2 (bias seeded in acc).
__device__ __forceinline__ float dot64p(const u64* __restrict__ w,
                                        const float* __restrict__ v,
                                        float bias)
{
    const ulonglong2* __restrict__ v2 = (const ulonglong2*)v;
    u64 a0 = pk(bias, 0.f), a1 = 0ull, a2 = 0ull, a3 = 0ull;
#pragma unroll
    for (int q = 0; q < 8; q++) {
        ulonglong2 p = v2[2*q];
        ulonglong2 r = v2[2*q + 1];
        a0 = fma2(w[4*q+0], p.x, a0);
        a1 = fma2(w[4*q+1], p.y, a1);
        a2 = fma2(w[4*q+2], r.x, a2);
        a3 = fma2(w[4*q+3], r.y, a3);
    }
    u64 s = add2(add2(a0, a1), add2(a2, a3));
    return __uint_as_float((unsigned)s) + __uint_as_float((unsigned)(s >> 32));
}

__device__ __forceinline__ float sigmoidf_(float a) {      // precise (gates)
    return __fdividef(1.f, 1.f + __expf(-a));
}
__device__ __forceinline__ float tanhf_fast(float x) {     // precise (n-gate)
    float e = __expf(2.f * x);
    return 1.f - __fdividef(2.f, e + 1.f);
}
__device__ __forceinline__ float tanh_ap(float x) {        // approx (t1 only)
    float y;
    asm("tanh.approx.f32 %0, %1;" : "=f"(y) : "f"(x));
    return y;
}

__global__ __launch_bounds__(256, 1)
void odegru_kernel(const float* __restrict__ x,
                   const float* __restrict__ tdel,
                   const int*   __restrict__ seq,
                   const float* __restrict__ h0,
                   const float* __restrict__ w_ih,
                   const float* __restrict__ w_hh,
                   const float* __restrict__ b_ih,
                   const float* __restrict__ b_hh,
                   const float* __restrict__ dw1,
                   const float* __restrict__ db1,
                   const float* __restrict__ dw2,
                   const float* __restrict__ db2,
                   float* __restrict__ out)
{
    const int b   = blockIdx.x;
    const int tid = threadIdx.x;

    __shared__ __align__(16) float sh_h[ND];
    __shared__ __align__(16) float sh_t1[ND];
    __shared__ __align__(16) float sh_ho[ND];
    __shared__ __align__(16) float sh_gx[NG];
    __shared__ __align__(16) float sh_gh[128];   // rows 0..127 (128+j in reg)
    __shared__ __align__(16) float sh_x[2][ND];
    __shared__ float sh_dt[2];

    // ---- packed weight rows (2/thread), identical role split to R5 ----
    // t0-63  : wX = dw1 row j        (P1)   wY = w_hh row 128+j (P3)
    // t64-127: wX = dw2 row j        (P2)   wY = w_ih row j     (P1)
    // t128-255:wX = w_hh row tid-128 (P3)   wY = w_ih row tid-64(P1)
    u64 wX[32], wY[32];
    float bX, bY;
    const float* pX;
    const float* pY;
    if (tid < 64) {
        pX = dw1 + tid * 64;          bX = db1[tid];
        pY = w_hh + (128 + tid) * 64; bY = b_hh[128 + tid];
    } else if (tid < 128) {
        int j = tid - 64;
        pX = dw2 + j * 64;            bX = db2[j];
        pY = w_ih + j * 64;           bY = b_ih[j];
    } else {
        pX = w_hh + (tid - 128) * 64; bX = b_hh[tid - 128];
        pY = w_ih + (tid - 64) * 64;  bY = b_ih[tid - 64];
    }
#pragma unroll
    for (int k = 0; k < 32; k++) {
        wX[k] = ((const u64*)pX)[k];
        wY[k] = ((const u64*)pY)[k];
    }

    const int sl = seq[b];
    const float* xb  = x + (size_t)b * NL * ND;
    const float* dtb = tdel + (size_t)b * NL;
    float* outb      = out + (size_t)b * NL * ND;

    if (tid < 64) sh_h[tid] = h0[tid];
    // prefetch registers: xA/dtA hold data for step t+1 (threads 64-127 own)
    float xA = 0.f, dtA = 0.f;
    if (tid >= 64 && tid < 128) {
        int j = tid - 64;
        sh_x[0][j] = xb[j];          // t=0 always live (sl >= 1)
        xA = xb[ND + j];             // x for t=1
        if (tid == 64) { sh_dt[0] = dtb[0]; dtA = dtb[1]; }
    }

    float fin = 0.f;
    __syncthreads();

    for (int t = 0; t < NL; t++) {
        const int cur = t & 1, nxt = cur ^ 1;
        const int tn  = t + 1;

        if (tid < 64) {
            const int j = tid;
            // ---- P1: t1 = tanh(h*dw1^T + db1) ----
            sh_t1[j] = tanh_ap(dot64p(wX, sh_h, bX));
            __syncthreads();                       // sync1

            // P2 idle window: preload gx (final since sync1)
            float gx0 = sh_gx[j];
            float gx1 = sh_gx[64 + j];
            float gx2 = sh_gx[128 + j];
            __syncthreads();                       // sync2

            // ---- P3: gh[128+j] in register; pick up ho alongside ----
            float ho = sh_ho[j];
            float gn = dot64p(wY, sh_ho, bY);
            __syncthreads();                       // sync3

            // ---- P4: gates ----
            float r  = sigmoidf_(gx0 + sh_gh[j]);
            float z  = sigmoidf_(gx1 + sh_gh[64 + j]);
            float n  = tanhf_fast(fmaf(r, gn, gx2));
            float hn = fmaf(z, ho - n, n);         // (1-z)*n + z*ho
            sh_h[j] = hn;
            outb[(size_t)t * ND + j] = hn;
            if (t == sl - 1) fin = hn;
            __syncthreads();                       // sync4
        } else if (tid < 128) {
            const int j = tid - 64;
            // ---- P1: gx rows 0..63 ----
            sh_gx[j] = dot64p(wY, sh_x[cur], bY);
            __syncthreads();                       // sync1

            // ---- P2: h_ode = h + (t1*dw2^T + db2)*dt ----
            float d = dot64p(wX, sh_t1, bX);
            sh_ho[j] = fmaf(d, sh_dt[cur], sh_h[j]);
            __syncthreads();                       // sync2

            // P3 idle window: commit x/dt for t+1, issue LDG for t+2.
            // sh_x[nxt] readers (gx, step t-1) finished at that step's sync1;
            // safe to write here. LDG->use distance ~ one full step.
            sh_x[nxt][j] = (tn < sl) ? xA : 0.f;   // PaddedBatch mask
            if (tid == 64) sh_dt[nxt] = (tn < sl) ? dtA : 0.f;
            if (t + 2 < NL) {
                xA = xb[(size_t)(t + 2) * ND + j];
                if (tid == 64) dtA = dtb[t + 2];
            }
            __syncthreads();                       // sync3
            __syncthreads();                       // sync4
        } else {
            // ---- P1: gx rows 64..191 ----
            sh_gx[tid - 64] = dot64p(wY, sh_x[cur], bY);
            __syncthreads();                       // sync1
            __syncthreads();                       // sync2

            // ---- P3: gh rows 0..127 ----
            sh_gh[tid - 128] = dot64p(wX, sh_ho, bX);
            __syncthreads();                       // sync3
            __syncthreads();                       // sync4
        }
    }

    // final hidden state -> second output tensor (1, B, D)
    if (tid < 64)
        out[(size_t)NB * NL * ND + (size_t)b * ND + tid] = fin;
}

extern "C" void kernel_launch(void* const* d_in, const int* in_sizes, int n_in,
                              void* d_out, int out_size)
{
    const float* x    = (const float*)d_in[0];
    const float* tdel = (const float*)d_in[1];
    const int*   seq  = (const int*)  d_in[2];
    const float* h0   = (const float*)d_in[3];
    const float* w_ih = (const float*)d_in[4];
    const float* w_hh = (const float*)d_in[5];
    const float* b_ih = (const float*)d_in[6];
    const float* b_hh = (const float*)d_in[7];
    const float* dw1  = (const float*)d_in[8];
    const float* db1  = (const float*)d_in[9];
    const float* dw2  = (const float*)d_in[10];
    const float* db2  = (const float*)d_in[11];

    odegru_kernel<<<NB, 256>>>(x, tdel, seq, h0, w_ih, w_hh, b_ih, b_hh,
                               dw1, db1, dw2, db2, (float*)d_out);
}

// round 12
// speedup vs baseline: 1.4563x; 1.0024x over previous
#include <cuda_runtime.h>
#include <cuda_bf16.h>

// ODE-GRU: B=128, L=2048, I=D=64.
// Round 12: R11 skeleton with PERFECT SMSP balance: every phase has exactly
// one warp-dot per SMSP (the 4-layer issue floor for 16 warp-dots/step).
//   P1: t1 (w0,w1)            || gx[0:64]    (w2,w3)
//   P2: hode (w2,w3)          || gx[64:128]  (w4,w5)
//   P3: gh[0:128] (w4,w5,w6,w7)   [w0,w1 preload gx/ho; w2,w3 commit x/dt]
//   P4: gn-dot + gates (w0,w1) || gx[128:192] for step t+1 (w6,w7)
// gx double-buffered (rows 128-191 produced one step early; prologue seeds
// t=0). tanh.approx for t1 (validated), precise gates. 4 full barriers.

#define NB 128
#define NL 2048
#define ND 64
#define NG 192

typedef unsigned long long u64;

__device__ __forceinline__ u64 fma2(u64 a, u64 b, u64 c) {
    u64 d;
    asm("fma.rn.f32x2 %0, %1, %2, %3;" : "=l"(d) : "l"(a), "l"(b), "l"(c));
    return d;
}
__device__ __forceinline__ u64 add2(u64 a, u64 b) {
    u64 d;
    asm("add.rn.f32x2 %0, %1, %2;" : "=l"(d) : "l"(a), "l"(b));
    return d;
}
__device__ __forceinline__ u64 pk(float lo, float hi) {
    u64 r;
    asm("mov.b64 %0, {%1, %2};" : "=l"(r) : "f"(lo), "f"(hi));
    return r;
}

// dot(w_row[64], v[64]) + bias, w pre-packed f32x2 (bias seeded in acc).
__device__ __forceinline__ float dot64p(const u64* __restrict__ w,
                                        const float* __restrict__ v,
                                        float bias)
{
    const ulonglong2* __restrict__ v2 = (const ulonglong2*)v;
    u64 a0 = pk(bias, 0.f), a1 = 0ull, a2 = 0ull, a3 = 0ull;
#pragma unroll
    for (int q = 0; q < 8; q++) {
        ulonglong2 p = v2[2*q];
        ulonglong2 r = v2[2*q + 1];
        a0 = fma2(w[4*q+0], p.x, a0);
        a1 = fma2(w[4*q+1], p.y, a1);
        a2 = fma2(w[4*q+2], r.x, a2);
        a3 = fma2(w[4*q+3], r.y, a3);
    }
    u64 s = add2(add2(a0, a1), add2(a2, a3));
    return __uint_as_float((unsigned)s) + __uint_as_float((unsigned)(s >> 32));
}

__device__ __forceinline__ float sigmoidf_(float a) {      // precise (gates)
    return __fdividef(1.f, 1.f + __expf(-a));
}
__device__ __forceinline__ float tanhf_fast(float x) {     // precise (n-gate)
    float e = __expf(2.f * x);
    return 1.f - __fdividef(2.f, e + 1.f);
}
__device__ __forceinline__ float tanh_ap(float x) {        // approx (t1 only)
    float y;
    asm("tanh.approx.f32 %0, %1;" : "=f"(y) : "f"(x));
    return y;
}

__global__ __launch_bounds__(256, 1)
void odegru_kernel(const float* __restrict__ x,
                   const float* __restrict__ tdel,
                   const int*   __restrict__ seq,
                   const float* __restrict__ h0,
                   const float* __restrict__ w_ih,
                   const float* __restrict__ w_hh,
                   const float* __restrict__ b_ih,
                   const float* __restrict__ b_hh,
                   const float* __restrict__ dw1,
                   const float* __restrict__ db1,
                   const float* __restrict__ dw2,
                   const float* __restrict__ db2,
                   float* __restrict__ out)
{
    const int b   = blockIdx.x;
    const int tid = threadIdx.x;

    __shared__ __align__(16) float sh_h[ND];
    __shared__ __align__(16) float sh_t1[ND];
    __shared__ __align__(16) float sh_ho[ND];
    __shared__ __align__(16) float sh_gx[2][NG];  // double-buffered by t&1
    __shared__ __align__(16) float sh_gh[128];    // rows 0..127 (128+j in reg)
    __shared__ __align__(16) float sh_x[2][ND];
    __shared__ float sh_dt[2];

    // ---- packed weight rows (2/thread) ----
    // w0,w1 (t  0- 63): wX=dw1 row j       wY=w_hh row 128+j  (t1 / gn)
    // w2,w3 (t 64-127): wX=dw2 row j       wY=w_ih row j      (hode / gx-r)
    // w4,w5 (t128-191): wX=w_hh row j      wY=w_ih row 64+j   (gh-r / gx-z)
    // w6,w7 (t192-255): wX=w_hh row 64+j   wY=w_ih row 128+j  (gh-z / gx-n)
    u64 wX[32], wY[32];
    float bX, bY;
    const float* pX;
    const float* pY;
    if (tid < 64) {
        pX = dw1 + tid * 64;            bX = db1[tid];
        pY = w_hh + (128 + tid) * 64;   bY = b_hh[128 + tid];
    } else if (tid < 128) {
        int j = tid - 64;
        pX = dw2 + j * 64;              bX = db2[j];
        pY = w_ih + j * 64;             bY = b_ih[j];
    } else if (tid < 192) {
        int j = tid - 128;
        pX = w_hh + j * 64;             bX = b_hh[j];
        pY = w_ih + (64 + j) * 64;      bY = b_ih[64 + j];
    } else {
        int j = tid - 192;
        pX = w_hh + (64 + j) * 64;      bX = b_hh[64 + j];
        pY = w_ih + (128 + j) * 64;     bY = b_ih[128 + j];
    }
#pragma unroll
    for (int k = 0; k < 32; k++) {
        wX[k] = ((const u64*)pX)[k];
        wY[k] = ((const u64*)pY)[k];
    }

    const int sl = seq[b];
    const float* xb  = x + (size_t)b * NL * ND;
    const float* dtb = tdel + (size_t)b * NL;
    float* outb      = out + (size_t)b * NL * ND;

    if (tid < 64) sh_h[tid] = h0[tid];
    float xA = 0.f, dtA = 0.f;                 // prefetch regs (w2,w3 own)
    if (tid >= 64 && tid < 128) {
        int j = tid - 64;
        sh_x[0][j] = xb[j];                    // t=0 always live (sl >= 1)
        xA = xb[ND + j];                       // x for t=1
        if (tid == 64) { sh_dt[0] = dtb[0]; dtA = dtb[1]; }
    }
    __syncthreads();

    // prologue: gx[t=0] rows 128..191 (in-loop these come from P4 of t-1)
    if (tid >= 192) {
        sh_gx[0][128 + (tid - 192)] = dot64p(wY, sh_x[0], bY);
    }

    float fin = 0.f;
    __syncthreads();

    for (int t = 0; t < NL; t++) {
        const int cur = t & 1, nxt = cur ^ 1;
        const int tn  = t + 1;

        if (tid < 64) {                       // ---- w0,w1 ----
            const int j = tid;
            // P1: t1 = tanh(h*dw1^T + db1)
            sh_t1[j] = tanh_ap(dot64p(wX, sh_h, bX));
            __syncthreads();                  // sync1
            // P2 idle: preload gx row-r (final since sync1)
            float gx0 = sh_gx[cur][j];
            __syncthreads();                  // sync2
            // P3 idle: preload gx z/n rows + ho
            float gx1 = sh_gx[cur][64 + j];
            float gx2 = sh_gx[cur][128 + j];
            float ho  = sh_ho[j];
            __syncthreads();                  // sync3
            // P4: gn dot + gates (r/z sigmoids overlap gn latency)
            float gn = dot64p(wY, sh_ho, bY);
            float r  = sigmoidf_(gx0 + sh_gh[j]);
            float z  = sigmoidf_(gx1 + sh_gh[64 + j]);
            float n  = tanhf_fast(fmaf(r, gn, gx2));
            float hn = fmaf(z, ho - n, n);    // (1-z)*n + z*ho
            sh_h[j] = hn;
            outb[(size_t)t * ND + j] = hn;
            if (t == sl - 1) fin = hn;
            __syncthreads();                  // sync4
        } else if (tid < 128) {               // ---- w2,w3 ----
            const int j = tid - 64;
            // P1: gx rows 0..63 for step t
            sh_gx[cur][j] = dot64p(wY, sh_x[cur], bY);
            __syncthreads();                  // sync1
            // P2: h_ode = h + (t1*dw2^T + db2)*dt
            float d = dot64p(wX, sh_t1, bX);
            sh_ho[j] = fmaf(d, sh_dt[cur], sh_h[j]);
            __syncthreads();                  // sync2
            // P3 window: commit x/dt for t+1, LDG for t+2 (~1 step cover)
            sh_x[nxt][j] = (tn < sl) ? xA : 0.f;    // PaddedBatch mask
            if (tid == 64) sh_dt[nxt] = (tn < sl) ? dtA : 0.f;
            if (t + 2 < NL) {
                xA = xb[(size_t)(t + 2) * ND + j];
                if (tid == 64) dtA = dtb[t + 2];
            }
            __syncthreads();                  // sync3
            __syncthreads();                  // sync4
        } else if (tid < 192) {               // ---- w4,w5 ----
            const int j = tid - 128;
            __syncthreads();                  // sync1
            // P2: gx rows 64..127 for step t
            sh_gx[cur][64 + j] = dot64p(wY, sh_x[cur], bY);
            __syncthreads();                  // sync2
            // P3: gh rows 0..63
            sh_gh[j] = dot64p(wX, sh_ho, bX);
            __syncthreads();                  // sync3
            __syncthreads();                  // sync4
        } else {                              // ---- w6,w7 ----
            const int j = tid - 192;
            __syncthreads();                  // sync1
            __syncthreads();                  // sync2
            // P3: gh rows 64..127
            sh_gh[64 + j] = dot64p(wX, sh_ho, bX);
            __syncthreads();                  // sync3
            // P4: gx rows 128..191 for step t+1 (x[t+1] committed pre-sync3)
            if (tn < NL)
                sh_gx[nxt][128 + j] = dot64p(wY, sh_x[nxt], bY);
            __syncthreads();                  // sync4
        }
    }

    // final hidden state -> second output tensor (1, B, D)
    if (tid < 64)
        out[(size_t)NB * NL * ND + (size_t)b * ND + tid] = fin;
}

extern "C" void kernel_launch(void* const* d_in, const int* in_sizes, int n_in,
                              void* d_out, int out_size)
{
    const float* x    = (const float*)d_in[0];
    const float* tdel = (const float*)d_in[1];
    const int*   seq  = (const int*)  d_in[2];
    const float* h0   = (const float*)d_in[3];
    const float* w_ih = (const float*)d_in[4];
    const float* w_hh = (const float*)d_in[5];
    const float* b_ih = (const float*)d_in[6];
    const float* b_hh = (const float*)d_in[7];
    const float* dw1  = (const float*)d_in[8];
    const float* db1  = (const float*)d_in[9];
    const float* dw2  = (const float*)d_in[10];
    const float* db2  = (const float*)d_in[11];

    odegru_kernel<<<NB, 256>>>(x, tdel, seq, h0, w_ih, w_hh, b_ih, b_hh,
                               dw1, db1, dw2, db2, (float*)d_out);
}